// round 15
// baseline (speedup 1.0000x reference)
#include <cuda_runtime.h>
#include <cuda_fp16.h>
#include <cstdint>

#define HPAD   66
#define CIN    128
#define OC     128
#define HW     4096
#define NB     4
#define NS     9
#define NCHUNK 18            /* 9 n x 2 channel-halves, K=64 fp16 per chunk */
#define STAGES 6

// ---- device scratch (16B-aligned via uint4) ----
__device__ uint4 g_xpad4[NB * HPAD * HPAD * CIN * 2 / 16 + 16]; // NHWC fp16 padded x
__device__ uint4 g_wk4[NS * 2 * OC * 64 * 2 / 16];              // [n][half][oc][64ch] fp16
__device__ float4 g_gw[NB * NS * HW];                           // bilinear weights
__device__ int4   g_go[NB * NS * HW];                           // gather BYTE offsets (idx*256)

// ---- dynamic smem layout (bytes) ----
#define SM_TPTR   0
#define SM_EMPTY(s) (16 + 8 * (s))
#define SM_A(s)   (1024 + (s) * 32768)          /* 128oc x 64ch fp16 = 16KB */
#define SM_B(s)   (SM_A(s) + 16384)             /* 128px x 64ch fp16 = 16KB */
#define SM_TS     1024
#define SM_TOTAL  (1024 + STAGES * 32768)

#define TMEM_COLS 128
// idesc kind::f16 (fp16 in, fp32 acc): dtype=F32(1)<<4, (N/8)<<17, (M/16)<<24
#define IDESC 0x8200010u

#define SW128(o) ((o) ^ (((o) >> 3) & 0x70))

#if !defined(__CUDA_ARCH__) || defined(__CUDA_ARCH_FEAT_SM103_ALL)
#define HAS_TCGEN05 1
#else
#define HAS_TCGEN05 0
#endif

// ---------------- PTX helpers ----------------
__device__ __forceinline__ uint32_t smem_u32(const void* p) {
    uint32_t a;
    asm("{ .reg .u64 t; cvta.to.shared.u64 t, %1; cvt.u32.u64 %0, t; }" : "=r"(a) : "l"(p));
    return a;
}
__device__ __forceinline__ uint64_t mkdesc(uint32_t addr) {
    const uint64_t base = (2ull << 61) | (1ull << 46) | (64ull << 32) | (1ull << 16);
    return base | ((uint64_t)(addr >> 4) & 0x3FFF);
}
__device__ __forceinline__ void mbar_init(uint32_t a, uint32_t cnt) {
    asm volatile("mbarrier.init.shared.b64 [%0], %1;" :: "r"(a), "r"(cnt) : "memory");
}
__device__ __forceinline__ void mbar_wait(uint32_t a, uint32_t par) {
    uint32_t done;
    asm volatile(
        "{\n\t.reg .pred p;\n\t"
        "mbarrier.try_wait.parity.acquire.cta.shared::cta.b64 p, [%1], %2;\n\t"
        "selp.b32 %0, 1, 0, p;\n\t}"
        : "=r"(done) : "r"(a), "r"(par) : "memory");
    if (!done) {
        asm volatile(
            "{\n\t.reg .pred P1;\n\t"
            "W%=:\n\t"
            "mbarrier.try_wait.parity.acquire.cta.shared::cta.b64 P1, [%0], %1, 0x989680;\n\t"
            "@P1 bra.uni D%=;\n\t"
            "bra.uni W%=;\n\t"
            "D%=:\n\t}"
            :: "r"(a), "r"(par) : "memory");
    }
}
__device__ __forceinline__ void nbar_arrive(int id, int cnt) {
    asm volatile("bar.arrive %0, %1;" :: "r"(id), "r"(cnt) : "memory");
}
__device__ __forceinline__ void nbar_sync(int id, int cnt) {
    asm volatile("bar.sync %0, %1;" :: "r"(id), "r"(cnt) : "memory");
}
__device__ __forceinline__ void sts128u(uint32_t a, uint4 v) {
    asm volatile("st.shared.v4.b32 [%0], {%1,%2,%3,%4};"
                 :: "r"(a), "r"(v.x), "r"(v.y), "r"(v.z), "r"(v.w) : "memory");
}
__device__ __forceinline__ float2 h2f(uint32_t h) {
    __half2 v = *(__half2*)&h;
    return __half22float2(v);
}
__device__ __forceinline__ uint32_t bil2(float4 cw, uint32_t w0, uint32_t w1,
                                         uint32_t w2, uint32_t w3) {
    float2 f0 = h2f(w0), f1 = h2f(w1), f2 = h2f(w2), f3 = h2f(w3);
    float rx = cw.x * f0.x + cw.y * f1.x + cw.z * f2.x + cw.w * f3.x;
    float ry = cw.x * f0.y + cw.y * f1.y + cw.z * f2.y + cw.w * f3.y;
    __half2 h = __floats2half2_rn(rx, ry);
    return *(uint32_t*)&h;
}

#if HAS_TCGEN05
__device__ __forceinline__ void mma_f16(uint32_t d, uint64_t ad, uint64_t bd, bool acc) {
    uint32_t e = acc ? 1u : 0u, z = 0u;
    asm volatile(
        "{\n\t.reg .pred p;\n\tsetp.ne.u32 p, %5, 0;\n\t"
        "tcgen05.mma.cta_group::1.kind::f16 [%0], %1, %2, %3, {%4,%4,%4,%4}, p;\n\t}"
        :: "r"(d), "l"(ad), "l"(bd), "r"(IDESC), "r"(z), "r"(e) : "memory");
}
__device__ __forceinline__ void mma_commit(uint32_t mbar) {
    asm volatile(
        "tcgen05.commit.cta_group::1.mbarrier::arrive::one.shared::cluster.b64 [%0];"
        :: "r"(mbar) : "memory");
}
__device__ __forceinline__ void ldtm32(uint32_t* r, uint32_t ta) {
    asm volatile(
        "tcgen05.ld.sync.aligned.32x32b.x32.b32 "
        "{%0,%1,%2,%3,%4,%5,%6,%7,%8,%9,%10,%11,%12,%13,%14,%15,"
        "%16,%17,%18,%19,%20,%21,%22,%23,%24,%25,%26,%27,%28,%29,%30,%31}, [%32];"
        : "=r"(r[0]),"=r"(r[1]),"=r"(r[2]),"=r"(r[3]),"=r"(r[4]),"=r"(r[5]),"=r"(r[6]),"=r"(r[7]),
          "=r"(r[8]),"=r"(r[9]),"=r"(r[10]),"=r"(r[11]),"=r"(r[12]),"=r"(r[13]),"=r"(r[14]),"=r"(r[15]),
          "=r"(r[16]),"=r"(r[17]),"=r"(r[18]),"=r"(r[19]),"=r"(r[20]),"=r"(r[21]),"=r"(r[22]),"=r"(r[23]),
          "=r"(r[24]),"=r"(r[25]),"=r"(r[26]),"=r"(r[27]),"=r"(r[28]),"=r"(r[29]),"=r"(r[30]),"=r"(r[31])
        : "r"(ta));
}
#endif

// -------- fused prep (512 thr): pad/transpose->fp16 (0..527) + wk/coef (528..815) --------
__global__ __launch_bounds__(512) void prep_kernel(const float* __restrict__ x,
                                                   const float* __restrict__ w,
                                                   const float* __restrict__ off) {
    __shared__ float ts[64 * 65];
    int bk  = blockIdx.x;
    int tid = threadIdx.x;
    if (bk < 528) {
        int half = bk & 1, ri = bk >> 1;
        int hp = ri % HPAD, b = ri / HPAD;
        bool irow = (hp >= 1 && hp <= 64);
        if (irow) {
            const float* xr = x + ((size_t)(b * CIN + half * 64)) * 4096 + (size_t)(hp - 1) * 64;
            #pragma unroll
            for (int i = 0; i < 8; i++) {
                int idx = tid + i * 512;
                int c = idx >> 6, wp = idx & 63;
                ts[c * 65 + wp] = xr[(size_t)c * 4096 + wp];
            }
        }
        __syncthreads();
        __half* orow = (__half*)g_xpad4 + ((size_t)(b * HPAD + hp)) * HPAD * CIN + half * 64;
        #pragma unroll
        for (int i = 0; i < 2; i++) {
            int idx = tid + i * 512;            // over 66*8 = 528 uint4
            if (idx >= 528) break;
            int wp = idx >> 3, g = idx & 7;
            uint4 v = make_uint4(0, 0, 0, 0);
            if (irow && wp >= 1 && wp <= 64) {
                int c = g * 8, wq = wp - 1;
                __half2 h0 = __floats2half2_rn(ts[(c+0)*65+wq], ts[(c+1)*65+wq]);
                __half2 h1 = __floats2half2_rn(ts[(c+2)*65+wq], ts[(c+3)*65+wq]);
                __half2 h2 = __floats2half2_rn(ts[(c+4)*65+wq], ts[(c+5)*65+wq]);
                __half2 h3 = __floats2half2_rn(ts[(c+6)*65+wq], ts[(c+7)*65+wq]);
                v.x = *(uint32_t*)&h0; v.y = *(uint32_t*)&h1;
                v.z = *(uint32_t*)&h2; v.w = *(uint32_t*)&h3;
            }
            *(uint4*)(orow + (size_t)wp * CIN + g * 8) = v;
        }
    } else {
        int t = (bk - 528) * 512 + tid;         // 288 blocks x 512 = 147456
        {   // weight: [n][half][oc][64] fp16 <- w[oc][c][n]
            int c  = t & 127;
            int oc = (t >> 7) & 127;
            int n  = t >> 14;
            __half* wk = (__half*)g_wk4;
            wk[(((size_t)n * 2 + (c >> 6)) * OC + oc) * 64 + (c & 63)] =
                __float2half_rn(w[(oc * CIN + c) * 9 + n]);
        }
        {   // coefs
            int pix = t & 4095;
            int n   = (t >> 12) % 9;
            int b   = t / (9 * 4096);
            int i   = pix >> 6, j = pix & 63;
            float ox = off[(b * 18 + 2 * n)     * HW + pix];
            float oy = off[(b * 18 + 2 * n + 1) * HW + pix];
            float px = (float)(i + n / 3) + ox;
            float py = (float)(j + n % 3) + oy;
            float fx = floorf(px), fy = floorf(py);
            int qltx = min(max((int)fx, 0), 65);
            int qlty = min(max((int)fy, 0), 65);
            int qrbx = min(max((int)fx + 1, 0), 65);
            int qrby = min(max((int)fy + 1, 0), 65);
            if (px < 1.f || px > 64.f) px = fx;
            if (py < 1.f || py > 64.f) py = fy;
            px = fminf(fmaxf(px, 0.f), 65.f);
            py = fminf(fmaxf(py, 0.f), 65.f);
            float dltx = 1.f + (float)qltx - px;
            float dlty = 1.f + (float)qlty - py;
            float drbx = 1.f - ((float)qrbx - px);
            float drby = 1.f - ((float)qrby - py);
            g_gw[t] = make_float4(dltx * dlty, drbx * drby, dltx * drby, drbx * dlty);
            // premultiplied byte offsets into NHWC fp16 plane (256 B per spatial pos)
            g_go[t] = make_int4((qltx * HPAD + qlty) << 8, (qrbx * HPAD + qrby) << 8,
                                (qltx * HPAD + qrby) << 8, (qrbx * HPAD + qlty) << 8);
        }
    }
}

// ------- main: 32 warps all build (free-running, named-barrier full), warp31 issues MMA ----
__global__ __launch_bounds__(1024, 1) void main_kernel(float* __restrict__ out) {
#if HAS_TCGEN05
    extern __shared__ char sm[];
    uint32_t smb = smem_u32(sm);
    int tid  = threadIdx.x;
    int wid  = tid >> 5;
    int lane = tid & 31;
    int b       = blockIdx.x >> 5;
    int pixbase = (blockIdx.x & 31) << 7;

    if (wid == 0)
        asm volatile("tcgen05.alloc.cta_group::1.sync.aligned.shared::cta.b32 [%0], %1;"
                     :: "r"(smb + SM_TPTR), "r"((uint32_t)TMEM_COLS) : "memory");
    if (tid == 0) {
        #pragma unroll
        for (int s = 0; s < STAGES; s++) mbar_init(smb + SM_EMPTY(s), 1);
    }
    __syncthreads();

    uint32_t tmem_base;
    asm volatile("ld.shared.b32 %0, [%1];" : "=r"(tmem_base) : "r"(smb + SM_TPTR));

    // slot: px = wid*4 + lane>>3 (0..127), c4 = lane&7 (16B channel group)
    int px = (wid << 2) + (lane >> 3);
    int c4 = lane & 7;
    uint32_t soff = SW128((uint32_t)(px * 128 + c4 * 16));

    const char* xb  = (const char*)g_xpad4 + (size_t)b * HPAD * HPAD * CIN * 2;
    const char* xc  = xb + c4 * 16;                  // + half*128 per chunk
    const char* wkp = (const char*)g_wk4 + px * 128 + c4 * 16;   // + j*16384 per chunk
    const float4* gwp = g_gw + ((size_t)b * NS) * HW + pixbase + px;
    const int4*   gop = g_go + ((size_t)b * NS) * HW + pixbase + px;

    float4 cw = make_float4(0.f, 0.f, 0.f, 0.f);
    int4   co = make_int4(0, 0, 0, 0);

    #pragma unroll 1
    for (int j = 0; j < NCHUNK; j++) {
        int s = j % STAGES;
        int half = j & 1;
        if (j >= STAGES) mbar_wait(smb + SM_EMPTY(s), ((j / STAGES) - 1) & 1);

        // ---- A tile: one 16B cp.async per thread; src advances linearly ----
        asm volatile("cp.async.cg.shared.global [%0], [%1], 16;"
                     :: "r"(smb + SM_A(s) + soff), "l"(wkp + (size_t)j * 16384) : "memory");
        asm volatile("cp.async.commit_group;" ::: "memory");

        // ---- coefs: reload per n (every 2 chunks); broadcast within 8-lane group ----
        if (half == 0) {
            cw = *gwp; co = *gop;
            gwp += HW; gop += HW;
        }

        // ---- B: 4 corner gathers (premultiplied offsets) + bilinear + one STS.128 ----
        {
            const char* xs = xc + half * 128;
            uint4 v0 = *(const uint4*)(xs + co.x);
            uint4 v1 = *(const uint4*)(xs + co.y);
            uint4 v2 = *(const uint4*)(xs + co.z);
            uint4 v3 = *(const uint4*)(xs + co.w);
            uint4 o;
            o.x = bil2(cw, v0.x, v1.x, v2.x, v3.x);
            o.y = bil2(cw, v0.y, v1.y, v2.y, v3.y);
            o.z = bil2(cw, v0.z, v1.z, v2.z, v3.z);
            o.w = bil2(cw, v0.w, v1.w, v2.w, v3.w);
            sts128u(smb + SM_B(s) + soff, o);
        }

        asm volatile("cp.async.wait_group 0;" ::: "memory");
        asm volatile("fence.proxy.async.shared::cta;" ::: "memory");

        if (wid == 31) {
            nbar_sync(1 + s, 1024);              // completes builders' arrivals
            if (lane == 0) {
                uint64_t ad = mkdesc(smb + SM_A(s));
                uint64_t bd = mkdesc(smb + SM_B(s));
                #pragma unroll
                for (int k = 0; k < 4; k++)      // K=64 = 4 x K16
                    mma_f16(tmem_base, ad + 2 * k, bd + 2 * k, (j > 0) || (k > 0));
                mma_commit(smb + SM_EMPTY(s));
            }
        } else {
            nbar_arrive(1 + s, 1024);            // non-blocking: builders free-run
        }
    }

    // final: last chunk j=17 -> stage 5, 3rd completion -> wait parity 0
    mbar_wait(smb + SM_EMPTY(STAGES - 1), (NCHUNK / STAGES - 1) & 1);
    asm volatile("tcgen05.fence::after_thread_sync;" ::: "memory");

    // ---- epilogue: TMEM -> smem transpose -> coalesced STG (Ts aliases ring stage 0) ----
    float* Ts = (float*)(sm + SM_TS);
    for (int cg = 0; cg < 4; cg++) {
        if (wid < 4) {
            uint32_t r[32];
            ldtm32(r, tmem_base + cg * 32);
            asm volatile("tcgen05.wait::ld.sync.aligned;" ::: "memory");
            int oc = wid * 32 + lane;
            #pragma unroll
            for (int c = 0; c < 32; c++) Ts[oc * 33 + c] = __uint_as_float(r[c]);
        }
        __syncthreads();
        {
            int ocr = tid >> 3, q4 = (tid & 7) * 4;
            const float* row = Ts + ocr * 33 + q4;
            float* op = out + ((size_t)(b * OC + ocr)) * HW + pixbase + cg * 32 + q4;
            *(float4*)op = make_float4(row[0], row[1], row[2], row[3]);
        }
        __syncthreads();
    }

    if (wid == 0) {
        asm volatile("tcgen05.relinquish_alloc_permit.cta_group::1.sync.aligned;");
        asm volatile("tcgen05.dealloc.cta_group::1.sync.aligned.b32 %0, %1;"
                     :: "r"(tmem_base), "r"((uint32_t)TMEM_COLS));
    }
#else
    (void)out;   // non-103a PTX pass: dead body; sm_103a cubin selected at runtime
#endif
}

// ---------------- launch ----------------
extern "C" void kernel_launch(void* const* d_in, const int* in_sizes, int n_in,
                              void* d_out, int out_size) {
    const float* x   = (const float*)d_in[0];
    const float* off = (const float*)d_in[1];
    const float* w   = (const float*)d_in[2];
    float* out = (float*)d_out;
    (void)in_sizes; (void)n_in; (void)out_size;

    cudaFuncSetAttribute(main_kernel, cudaFuncAttributeMaxDynamicSharedMemorySize, SM_TOTAL);

    prep_kernel<<<528 + 288, 512>>>(x, w, off);
    main_kernel<<<128, 1024, SM_TOTAL>>>(out);
}

// round 16
// speedup vs baseline: 1.0780x; 1.0780x over previous
#include <cuda_runtime.h>
#include <cuda_fp16.h>
#include <cstdint>

#define HPAD   66
#define CIN    128
#define OC     128
#define HW     4096
#define NB     4
#define NS     9
#define NCHUNK 18            /* 9 n x 2 channel-halves, K=64 fp16 per chunk */
#define STAGES 6

// ---- device scratch (16B-aligned via uint4) ----
__device__ uint4 g_xpad4[NB * HPAD * HPAD * CIN * 2 / 16 + 16]; // NHWC fp16 padded x
__device__ uint4 g_wk4[NS * 2 * OC * 64 * 2 / 16];              // [n][half][oc][64ch] fp16
__device__ float4 g_gw[NB * NS * HW];                           // bilinear weights
__device__ int4   g_go[NB * NS * HW];                           // gather BYTE offsets (idx*256)

// ---- dynamic smem layout (bytes) ----
#define SM_TPTR   0
#define SM_EMPTY(s) (16 + 8 * (s))
#define SM_A(s)   (1024 + (s) * 32768)          /* 128oc x 64ch fp16 = 16KB */
#define SM_B(s)   (SM_A(s) + 16384)             /* 128px x 64ch fp16 = 16KB */
#define SM_TS     1024
#define SM_TOTAL  (1024 + STAGES * 32768)

#define TMEM_COLS 128
// idesc kind::f16 (fp16 in, fp32 acc): dtype=F32(1)<<4, (N/8)<<17, (M/16)<<24
#define IDESC 0x8200010u

#define SW128(o) ((o) ^ (((o) >> 3) & 0x70))

#if !defined(__CUDA_ARCH__) || defined(__CUDA_ARCH_FEAT_SM103_ALL)
#define HAS_TCGEN05 1
#else
#define HAS_TCGEN05 0
#endif

// ---------------- PTX helpers ----------------
__device__ __forceinline__ uint32_t smem_u32(const void* p) {
    uint32_t a;
    asm("{ .reg .u64 t; cvta.to.shared.u64 t, %1; cvt.u32.u64 %0, t; }" : "=r"(a) : "l"(p));
    return a;
}
__device__ __forceinline__ uint64_t mkdesc(uint32_t addr) {
    const uint64_t base = (2ull << 61) | (1ull << 46) | (64ull << 32) | (1ull << 16);
    return base | ((uint64_t)(addr >> 4) & 0x3FFF);
}
__device__ __forceinline__ void mbar_init(uint32_t a, uint32_t cnt) {
    asm volatile("mbarrier.init.shared.b64 [%0], %1;" :: "r"(a), "r"(cnt) : "memory");
}
__device__ __forceinline__ void mbar_wait(uint32_t a, uint32_t par) {
    uint32_t done;
    asm volatile(
        "{\n\t.reg .pred p;\n\t"
        "mbarrier.try_wait.parity.acquire.cta.shared::cta.b64 p, [%1], %2;\n\t"
        "selp.b32 %0, 1, 0, p;\n\t}"
        : "=r"(done) : "r"(a), "r"(par) : "memory");
    if (!done) {
        asm volatile(
            "{\n\t.reg .pred P1;\n\t"
            "W%=:\n\t"
            "mbarrier.try_wait.parity.acquire.cta.shared::cta.b64 P1, [%0], %1, 0x989680;\n\t"
            "@P1 bra.uni D%=;\n\t"
            "bra.uni W%=;\n\t"
            "D%=:\n\t}"
            :: "r"(a), "r"(par) : "memory");
    }
}
__device__ __forceinline__ void nbar_arrive(int id, int cnt) {
    asm volatile("bar.arrive %0, %1;" :: "r"(id), "r"(cnt) : "memory");
}
__device__ __forceinline__ void nbar_sync(int id, int cnt) {
    asm volatile("bar.sync %0, %1;" :: "r"(id), "r"(cnt) : "memory");
}
__device__ __forceinline__ void sts128u(uint32_t a, uint4 v) {
    asm volatile("st.shared.v4.b32 [%0], {%1,%2,%3,%4};"
                 :: "r"(a), "r"(v.x), "r"(v.y), "r"(v.z), "r"(v.w) : "memory");
}
__device__ __forceinline__ float2 h2f(uint32_t h) {
    __half2 v = *(__half2*)&h;
    return __half22float2(v);
}
__device__ __forceinline__ uint32_t bil2(float4 cw, uint32_t w0, uint32_t w1,
                                         uint32_t w2, uint32_t w3) {
    float2 f0 = h2f(w0), f1 = h2f(w1), f2 = h2f(w2), f3 = h2f(w3);
    float rx = cw.x * f0.x + cw.y * f1.x + cw.z * f2.x + cw.w * f3.x;
    float ry = cw.x * f0.y + cw.y * f1.y + cw.z * f2.y + cw.w * f3.y;
    __half2 h = __floats2half2_rn(rx, ry);
    return *(uint32_t*)&h;
}

#if HAS_TCGEN05
__device__ __forceinline__ void mma_f16(uint32_t d, uint64_t ad, uint64_t bd, bool acc) {
    uint32_t e = acc ? 1u : 0u, z = 0u;
    asm volatile(
        "{\n\t.reg .pred p;\n\tsetp.ne.u32 p, %5, 0;\n\t"
        "tcgen05.mma.cta_group::1.kind::f16 [%0], %1, %2, %3, {%4,%4,%4,%4}, p;\n\t}"
        :: "r"(d), "l"(ad), "l"(bd), "r"(IDESC), "r"(z), "r"(e) : "memory");
}
__device__ __forceinline__ void mma_commit(uint32_t mbar) {
    asm volatile(
        "tcgen05.commit.cta_group::1.mbarrier::arrive::one.shared::cluster.b64 [%0];"
        :: "r"(mbar) : "memory");
}
__device__ __forceinline__ void ldtm32(uint32_t* r, uint32_t ta) {
    asm volatile(
        "tcgen05.ld.sync.aligned.32x32b.x32.b32 "
        "{%0,%1,%2,%3,%4,%5,%6,%7,%8,%9,%10,%11,%12,%13,%14,%15,"
        "%16,%17,%18,%19,%20,%21,%22,%23,%24,%25,%26,%27,%28,%29,%30,%31}, [%32];"
        : "=r"(r[0]),"=r"(r[1]),"=r"(r[2]),"=r"(r[3]),"=r"(r[4]),"=r"(r[5]),"=r"(r[6]),"=r"(r[7]),
          "=r"(r[8]),"=r"(r[9]),"=r"(r[10]),"=r"(r[11]),"=r"(r[12]),"=r"(r[13]),"=r"(r[14]),"=r"(r[15]),
          "=r"(r[16]),"=r"(r[17]),"=r"(r[18]),"=r"(r[19]),"=r"(r[20]),"=r"(r[21]),"=r"(r[22]),"=r"(r[23]),
          "=r"(r[24]),"=r"(r[25]),"=r"(r[26]),"=r"(r[27]),"=r"(r[28]),"=r"(r[29]),"=r"(r[30]),"=r"(r[31])
        : "r"(ta));
}
#endif

// -------- fused prep (512 thr): pad/transpose->fp16 (0..527) + wk/coef (528..815) --------
__global__ __launch_bounds__(512) void prep_kernel(const float* __restrict__ x,
                                                   const float* __restrict__ w,
                                                   const float* __restrict__ off) {
    __shared__ float ts[64 * 65];
    int bk  = blockIdx.x;
    int tid = threadIdx.x;
    if (bk < 528) {
        int half = bk & 1, ri = bk >> 1;
        int hp = ri % HPAD, b = ri / HPAD;
        bool irow = (hp >= 1 && hp <= 64);
        if (irow) {
            const float* xr = x + ((size_t)(b * CIN + half * 64)) * 4096 + (size_t)(hp - 1) * 64;
            #pragma unroll
            for (int i = 0; i < 8; i++) {
                int idx = tid + i * 512;
                int c = idx >> 6, wp = idx & 63;
                ts[c * 65 + wp] = xr[(size_t)c * 4096 + wp];
            }
        }
        __syncthreads();
        __half* orow = (__half*)g_xpad4 + ((size_t)(b * HPAD + hp)) * HPAD * CIN + half * 64;
        #pragma unroll
        for (int i = 0; i < 2; i++) {
            int idx = tid + i * 512;            // over 66*8 = 528 uint4
            if (idx >= 528) break;
            int wp = idx >> 3, g = idx & 7;
            uint4 v = make_uint4(0, 0, 0, 0);
            if (irow && wp >= 1 && wp <= 64) {
                int c = g * 8, wq = wp - 1;
                __half2 h0 = __floats2half2_rn(ts[(c+0)*65+wq], ts[(c+1)*65+wq]);
                __half2 h1 = __floats2half2_rn(ts[(c+2)*65+wq], ts[(c+3)*65+wq]);
                __half2 h2 = __floats2half2_rn(ts[(c+4)*65+wq], ts[(c+5)*65+wq]);
                __half2 h3 = __floats2half2_rn(ts[(c+6)*65+wq], ts[(c+7)*65+wq]);
                v.x = *(uint32_t*)&h0; v.y = *(uint32_t*)&h1;
                v.z = *(uint32_t*)&h2; v.w = *(uint32_t*)&h3;
            }
            *(uint4*)(orow + (size_t)wp * CIN + g * 8) = v;
        }
    } else {
        int t = (bk - 528) * 512 + tid;         // 288 blocks x 512 = 147456
        {   // weight: [n][half][oc][64] fp16 <- w[oc][c][n]
            int c  = t & 127;
            int oc = (t >> 7) & 127;
            int n  = t >> 14;
            __half* wk = (__half*)g_wk4;
            wk[(((size_t)n * 2 + (c >> 6)) * OC + oc) * 64 + (c & 63)] =
                __float2half_rn(w[(oc * CIN + c) * 9 + n]);
        }
        {   // coefs
            int pix = t & 4095;
            int n   = (t >> 12) % 9;
            int b   = t / (9 * 4096);
            int i   = pix >> 6, j = pix & 63;
            float ox = off[(b * 18 + 2 * n)     * HW + pix];
            float oy = off[(b * 18 + 2 * n + 1) * HW + pix];
            float px = (float)(i + n / 3) + ox;
            float py = (float)(j + n % 3) + oy;
            float fx = floorf(px), fy = floorf(py);
            int qltx = min(max((int)fx, 0), 65);
            int qlty = min(max((int)fy, 0), 65);
            int qrbx = min(max((int)fx + 1, 0), 65);
            int qrby = min(max((int)fy + 1, 0), 65);
            if (px < 1.f || px > 64.f) px = fx;
            if (py < 1.f || py > 64.f) py = fy;
            px = fminf(fmaxf(px, 0.f), 65.f);
            py = fminf(fmaxf(py, 0.f), 65.f);
            float dltx = 1.f + (float)qltx - px;
            float dlty = 1.f + (float)qlty - py;
            float drbx = 1.f - ((float)qrbx - px);
            float drby = 1.f - ((float)qrby - py);
            g_gw[t] = make_float4(dltx * dlty, drbx * drby, dltx * drby, drbx * dlty);
            // premultiplied byte offsets into NHWC fp16 plane (256 B per spatial pos)
            g_go[t] = make_int4((qltx * HPAD + qlty) << 8, (qrbx * HPAD + qrby) << 8,
                                (qltx * HPAD + qrby) << 8, (qrbx * HPAD + qlty) << 8);
        }
    }
}

// ------- main: 32 warps build chunk PAIRS (both halves of n), warp31 issues MMA ----------
__global__ __launch_bounds__(1024, 1) void main_kernel(float* __restrict__ out) {
#if HAS_TCGEN05
    extern __shared__ char sm[];
    uint32_t smb = smem_u32(sm);
    int tid  = threadIdx.x;
    int wid  = tid >> 5;
    int lane = tid & 31;
    int b       = blockIdx.x >> 5;
    int pixbase = (blockIdx.x & 31) << 7;

    if (wid == 0)
        asm volatile("tcgen05.alloc.cta_group::1.sync.aligned.shared::cta.b32 [%0], %1;"
                     :: "r"(smb + SM_TPTR), "r"((uint32_t)TMEM_COLS) : "memory");
    if (tid == 0) {
        #pragma unroll
        for (int s = 0; s < STAGES; s++) mbar_init(smb + SM_EMPTY(s), 1);
    }
    __syncthreads();

    uint32_t tmem_base;
    asm volatile("ld.shared.b32 %0, [%1];" : "=r"(tmem_base) : "r"(smb + SM_TPTR));

    // slot: px = wid*4 + lane>>3 (0..127), c4 = lane&7 (16B channel group)
    int px = (wid << 2) + (lane >> 3);
    int c4 = lane & 7;
    uint32_t soff = SW128((uint32_t)(px * 128 + c4 * 16));

    const char* xb  = (const char*)g_xpad4 + (size_t)b * HPAD * HPAD * CIN * 2;
    const char* xc  = xb + c4 * 16;                  // + half*128 per chunk
    const char* wkp = (const char*)g_wk4 + px * 128 + c4 * 16;   // + j*16384 per chunk
    const float4* gwp = g_gw + ((size_t)b * NS) * HW + pixbase + px;
    const int4*   gop = g_go + ((size_t)b * NS) * HW + pixbase + px;

    #pragma unroll 1
    for (int m = 0; m < 9; m++) {
        int s0 = (m % 3) * 2;                        // stage pair (s0, s0+1)
        uint32_t A0 = smb + SM_A(s0),      A1 = A0 + 32768;
        uint32_t B0 = smb + SM_B(s0),      B1 = B0 + 32768;
        uint32_t e0 = smb + SM_EMPTY(s0),  e1 = e0 + 8;

        if (m >= 3) {                                // reuse ring after 3 pairs (6 chunks)
            int par = (m / 3 - 1) & 1;
            mbar_wait(e0, par);
            mbar_wait(e1, par);
        }

        // ---- A tiles for both halves via cp.async ----
        const char* wsrc = wkp + (size_t)(2 * m) * 16384;
        asm volatile("cp.async.cg.shared.global [%0], [%1], 16;"
                     :: "r"(A0 + soff), "l"(wsrc) : "memory");
        asm volatile("cp.async.cg.shared.global [%0], [%1], 16;"
                     :: "r"(A1 + soff), "l"(wsrc + 16384) : "memory");
        asm volatile("cp.async.commit_group;" ::: "memory");

        // ---- coefs: once per n; broadcast within 8-lane group ----
        float4 cw = *gwp; int4 co = *gop;
        gwp += HW; gop += HW;

        // ---- B: 8 corner gathers (both halves) issued together, then bilinear ----
        uint4 v0 = *(const uint4*)(xc + co.x);
        uint4 v1 = *(const uint4*)(xc + co.y);
        uint4 v2 = *(const uint4*)(xc + co.z);
        uint4 v3 = *(const uint4*)(xc + co.w);
        uint4 u0 = *(const uint4*)(xc + 128 + co.x);
        uint4 u1 = *(const uint4*)(xc + 128 + co.y);
        uint4 u2 = *(const uint4*)(xc + 128 + co.z);
        uint4 u3 = *(const uint4*)(xc + 128 + co.w);
        uint4 o0, o1;
        o0.x = bil2(cw, v0.x, v1.x, v2.x, v3.x);
        o0.y = bil2(cw, v0.y, v1.y, v2.y, v3.y);
        o0.z = bil2(cw, v0.z, v1.z, v2.z, v3.z);
        o0.w = bil2(cw, v0.w, v1.w, v2.w, v3.w);
        o1.x = bil2(cw, u0.x, u1.x, u2.x, u3.x);
        o1.y = bil2(cw, u0.y, u1.y, u2.y, u3.y);
        o1.z = bil2(cw, u0.z, u1.z, u2.z, u3.z);
        o1.w = bil2(cw, u0.w, u1.w, u2.w, u3.w);
        sts128u(B0 + soff, o0);
        sts128u(B1 + soff, o1);

        asm volatile("cp.async.wait_group 0;" ::: "memory");
        asm volatile("fence.proxy.async.shared::cta;" ::: "memory");

        if (wid == 31) {
            nbar_sync(1 + s0, 1024);
            if (lane == 0) {
                uint64_t ad = mkdesc(A0), bd = mkdesc(B0);
                #pragma unroll
                for (int k = 0; k < 4; k++)
                    mma_f16(tmem_base, ad + 2 * k, bd + 2 * k, (m > 0) || (k > 0));
                mma_commit(e0);
            }
            nbar_sync(2 + s0, 1024);
            if (lane == 0) {
                uint64_t ad = mkdesc(A1), bd = mkdesc(B1);
                #pragma unroll
                for (int k = 0; k < 4; k++)
                    mma_f16(tmem_base, ad + 2 * k, bd + 2 * k, true);
                mma_commit(e1);
            }
        } else {
            nbar_arrive(1 + s0, 1024);
            nbar_arrive(2 + s0, 1024);
        }
    }

    // final: last chunk j=17 -> stage 5, 3rd completion -> wait parity (3-1)&1 = 0
    mbar_wait(smb + SM_EMPTY(STAGES - 1), (NCHUNK / STAGES - 1) & 1);
    asm volatile("tcgen05.fence::after_thread_sync;" ::: "memory");

    // ---- epilogue: TMEM -> smem transpose -> coalesced STG (Ts aliases ring stage 0) ----
    float* Ts = (float*)(sm + SM_TS);
    for (int cg = 0; cg < 4; cg++) {
        if (wid < 4) {
            uint32_t r[32];
            ldtm32(r, tmem_base + cg * 32);
            asm volatile("tcgen05.wait::ld.sync.aligned;" ::: "memory");
            int oc = wid * 32 + lane;
            #pragma unroll
            for (int c = 0; c < 32; c++) Ts[oc * 33 + c] = __uint_as_float(r[c]);
        }
        __syncthreads();
        {
            int ocr = tid >> 3, q4 = (tid & 7) * 4;
            const float* row = Ts + ocr * 33 + q4;
            float* op = out + ((size_t)(b * OC + ocr)) * HW + pixbase + cg * 32 + q4;
            *(float4*)op = make_float4(row[0], row[1], row[2], row[3]);
        }
        __syncthreads();
    }

    if (wid == 0) {
        asm volatile("tcgen05.relinquish_alloc_permit.cta_group::1.sync.aligned;");
        asm volatile("tcgen05.dealloc.cta_group::1.sync.aligned.b32 %0, %1;"
                     :: "r"(tmem_base), "r"((uint32_t)TMEM_COLS));
    }
#else
    (void)out;   // non-103a PTX pass: dead body; sm_103a cubin selected at runtime
#endif
}

// ---------------- launch ----------------
extern "C" void kernel_launch(void* const* d_in, const int* in_sizes, int n_in,
                              void* d_out, int out_size) {
    const float* x   = (const float*)d_in[0];
    const float* off = (const float*)d_in[1];
    const float* w   = (const float*)d_in[2];
    float* out = (float*)d_out;
    (void)in_sizes; (void)n_in; (void)out_size;

    cudaFuncSetAttribute(main_kernel, cudaFuncAttributeMaxDynamicSharedMemorySize, SM_TOTAL);

    prep_kernel<<<528 + 288, 512>>>(x, w, off);
    main_kernel<<<128, 1024, SM_TOTAL>>>(out);
}